// round 5
// baseline (speedup 1.0000x reference)
#include <cuda_runtime.h>
#include <cuda_fp16.h>

#define NN 10000
#define FI 256
#define FO 64
#define BM 128
#define BN 64
#define NSPLIT 8
#define RT 79          // ceil(NN/BM)
#define NT 157         // ceil(NN/BN)
#define ALPHAS 0.2f

// ---------------- device scratch (no allocation allowed) ----------------
__device__ float g_Wh[NN * FO];
__device__ __half g_WhT[(size_t)FO * NN];     // n-major fp16 Wh^T
__device__ float g_f1[NN];
__device__ float g_f2[NN];
__device__ float g_pacc[(size_t)NSPLIT * RT * BM * FO];
__device__ float g_pden[NSPLIT * RT * BM];

// ---------------- smem layout (bytes) ----------------
#define PSTB 144                        // P: 128B data + 16B pad (conflict-free ldmatrix)
#define ADJST 288                       // adj row: 2 halves of 128B at offsets 0 / 144
#define SM_F2   0                       // 64 floats
#define SM_DEN  256                     // 128 floats
#define SM_P    768                     // 128 * 144 = 18432
#define SM_B    (SM_P + BM * PSTB)      // 19200, 64 * 144 = 9216
#define SM_ADJ0 (SM_B + FO * PSTB)      // 28416, 128 * 288 = 36864
#define SM_ADJ1 (SM_ADJ0 + BM * ADJST)  // 65280
#define SM_TOTAL (SM_ADJ1 + BM * ADJST) // 102144 (~99.8 KB)

// ---------------- PTX helpers ----------------
__device__ __forceinline__ unsigned s2u(const void* p) {
    unsigned a;
    asm("{ .reg .u64 t; cvta.to.shared.u64 t, %1; cvt.u32.u64 %0, t; }"
        : "=r"(a) : "l"(p));
    return a;
}
__device__ __forceinline__ void ldsm4(unsigned* r, unsigned addr) {
    asm volatile("ldmatrix.sync.aligned.m8n8.x4.shared.b16 {%0,%1,%2,%3}, [%4];"
                 : "=r"(r[0]), "=r"(r[1]), "=r"(r[2]), "=r"(r[3]) : "r"(addr));
}
__device__ __forceinline__ void hmma(float* c, const unsigned* a, const unsigned* b) {
    asm volatile(
        "mma.sync.aligned.m16n8k16.row.col.f32.f16.f16.f32 "
        "{%0,%1,%2,%3}, {%4,%5,%6,%7}, {%8,%9}, {%0,%1,%2,%3};"
        : "+f"(c[0]), "+f"(c[1]), "+f"(c[2]), "+f"(c[3])
        : "r"(a[0]), "r"(a[1]), "r"(a[2]), "r"(a[3]), "r"(b[0]), "r"(b[1]));
}
__device__ __forceinline__ void cp16(unsigned dst, const void* src, unsigned sz) {
    asm volatile("cp.async.cg.shared.global [%0], [%1], 16, %2;"
                 :: "r"(dst), "l"(src), "r"(sz) : "memory");
}
__device__ __forceinline__ void cp_commit() {
    asm volatile("cp.async.commit_group;" ::: "memory");
}
__device__ __forceinline__ void cp_wait1() {
    asm volatile("cp.async.wait_group 1;" ::: "memory");
}

// ---------------- Kernel 1: Wh = h @ W  (+ fp16 Wh^T) ----------------
__global__ __launch_bounds__(256) void wh_kernel(const float* __restrict__ h,
                                                 const float* __restrict__ W) {
    __shared__ float sh[16 * FI];
    int row0 = blockIdx.x * 16;
    const float* hp = h + (long long)row0 * FI;
    for (int t = threadIdx.x; t < 16 * FI; t += 256) sh[t] = hp[t];
    __syncthreads();
    int c = threadIdx.x & 63;
    int ty = threadIdx.x >> 6;   // 4 consecutive rows per thread
    float acc[4] = {0.f, 0.f, 0.f, 0.f};
    for (int k = 0; k < FI; ++k) {
        float w = W[k * FO + c];
        acc[0] += sh[(ty * 4 + 0) * FI + k] * w;
        acc[1] += sh[(ty * 4 + 1) * FI + k] * w;
        acc[2] += sh[(ty * 4 + 2) * FI + k] * w;
        acc[3] += sh[(ty * 4 + 3) * FI + k] * w;
    }
    __half hb[4];
    #pragma unroll
    for (int q = 0; q < 4; ++q) {
        int row = row0 + ty * 4 + q;
        g_Wh[row * FO + c] = acc[q];
        hb[q] = __float2half_rn(acc[q]);
    }
    size_t off = (size_t)c * NN + row0 + ty * 4;   // 4 consecutive j -> 8B store
    *(uint2*)&g_WhT[off] = *(uint2*)hb;
}

// ---------------- Kernel 2: f1/f2 ----------------
__global__ __launch_bounds__(128) void f12_kernel(const float* __restrict__ a) {
    int row = blockIdx.x * 4 + (threadIdx.x >> 5);
    int lane = threadIdx.x & 31;
    float w0 = g_Wh[row * FO + lane];
    float w1 = g_Wh[row * FO + 32 + lane];
    float s1 = w0 * a[lane] + w1 * a[lane + 32];
    float s2 = w0 * a[FO + lane] + w1 * a[FO + 32 + lane];
    #pragma unroll
    for (int o = 16; o > 0; o >>= 1) {
        s1 += __shfl_xor_sync(0xffffffffu, s1, o);
        s2 += __shfl_xor_sync(0xffffffffu, s2, o);
    }
    if (lane == 0) { g_f1[row] = s1; g_f2[row] = s2; }
}

// ---------------- Kernel 3: fused P-gen + fp16 mma.sync GEMM --------------
__global__ __launch_bounds__(256, 2) void gat_mma(const int* __restrict__ adj) {
    extern __shared__ char smem[];
    const unsigned sb = s2u(smem);
    float* sf2 = (float*)(smem + SM_F2);
    float* sden = (float*)(smem + SM_DEN);

    const int tid = threadIdx.x, wid = tid >> 5, lane = tid & 31;
    const int mt = blockIdx.x, jq = blockIdx.y;
    const int i0 = mt * BM;

    // P-gen mapping: thread -> (row r, 32-col half hh)
    const int r = tid >> 1, hh = tid & 1;
    const int i = i0 + r;
    const bool rowok = (i < NN);
    const float f1v = rowok ? g_f1[i] : 0.f;
    const int* arow = adj + (size_t)i * NN;
    const unsigned adj_dst = sb + r * ADJST + hh * 144;   // + SM_ADJx later

    // B-stage mapping: thread -> (c row, 16-half segment)
    const int bc = tid >> 2, bseg = tid & 3;

    // MMA fragment addressing
    const int m0 = wid * 16;
    const unsigned a_addr = sb + SM_P +
        (m0 + (lane & 7) + ((lane >> 3) & 1) * 8) * PSTB + (lane >> 4) * 16;
    const unsigned b_addr = sb + SM_B +
        ((lane & 7) + ((lane >> 4) & 1) * 8) * PSTB + ((lane >> 3) & 1) * 16;

    float acc[8][4];
    #pragma unroll
    for (int nt = 0; nt < 8; ++nt)
        #pragma unroll
        for (int q = 0; q < 4; ++q) acc[nt][q] = 0.f;

    if (tid < BM) sden[tid] = 0.f;

    // ---- prologue: async-copy first adj tile into buffer 0 ----
    {
        const int jb = jq * BN + hh * 32;
        #pragma unroll
        for (int u = 0; u < 8; ++u) {
            int j = jb + u * 4;
            unsigned sz = (rowok && (j + 3 < NN)) ? 16u : 0u;
            cp16(adj_dst + SM_ADJ0 + u * 16, arow + j, sz);
        }
    }
    cp_commit();

    int b = 0;
    for (int t = jq; t < NT; t += NSPLIT, b ^= 1) {
        const int j0 = t * BN;
        __syncthreads();   // prev MMA done (sP/sB free); buf b^1 consumed

        // ---- issue next tile's adj copy into the other buffer ----
        if (t + NSPLIT < NT) {
            const int jb = (t + NSPLIT) * BN + hh * 32;
            const unsigned dst = adj_dst + (b ? SM_ADJ0 : SM_ADJ1);
            #pragma unroll
            for (int u = 0; u < 8; ++u) {
                int j = jb + u * 4;
                unsigned sz = (rowok && (j + 3 < NN)) ? 16u : 0u;
                cp16(dst + u * 16, arow + j, sz);
            }
        }
        cp_commit();

        // ---- stage B tile (WhT fp16, n-major, padded rows) + f2 ----
        #pragma unroll
        for (int ch = 0; ch < 2; ++ch) {
            int e0 = bseg * 16 + ch * 8;
            uint4 v = make_uint4(0, 0, 0, 0);
            if (j0 + e0 + 7 < NN)
                v = *(const uint4*)(g_WhT + (size_t)bc * NN + j0 + e0);
            *(uint4*)(smem + SM_B + bc * PSTB + e0 * 2) = v;
        }
        if (tid < BN) sf2[tid] = (j0 + tid < NN) ? g_f2[j0 + tid] : 0.f;

        cp_wait1();        // adj(t) resident (next tile's group may still fly)
        __syncthreads();

        // ---- generate P tile (fp16) + denominator from ROUNDED p ----
        const char* sadj = smem + (b ? SM_ADJ1 : SM_ADJ0) + r * ADJST + hh * 144;
        float rsum = 0.f;
        #pragma unroll
        for (int u = 0; u < 8; ++u) {
            int4 m = *(const int4*)(sadj + u * 16);
            float4 f2q = *(const float4*)&sf2[hh * 32 + u * 4];
            float s, p0, p1, p2, p3;
            s = f1v + f2q.x; s = fmaxf(s, ALPHAS * s); p0 = m.x ? __expf(s) : 0.f;
            s = f1v + f2q.y; s = fmaxf(s, ALPHAS * s); p1 = m.y ? __expf(s) : 0.f;
            s = f1v + f2q.z; s = fmaxf(s, ALPHAS * s); p2 = m.z ? __expf(s) : 0.f;
            s = f1v + f2q.w; s = fmaxf(s, ALPHAS * s); p3 = m.w ? __expf(s) : 0.f;
            __half2 h01 = __floats2half2_rn(p0, p1);
            __half2 h23 = __floats2half2_rn(p2, p3);
            *(uint2*)(smem + SM_P + r * PSTB + hh * 64 + u * 8) =
                make_uint2(*(unsigned*)&h01, *(unsigned*)&h23);
            float2 b01 = __half22float2(h01);
            float2 b23 = __half22float2(h23);
            rsum += (b01.x + b01.y) + (b23.x + b23.y);
        }
        rsum += __shfl_down_sync(0xffffffffu, rsum, 1);
        if (!hh) sden[r] += rsum;   // unique owner thread per row
        __syncthreads();

        // ---- MMA: C += P @ WhT (single fp16 product) ----
        #pragma unroll
        for (int ks = 0; ks < 4; ++ks) {
            unsigned a[4];
            ldsm4(a, a_addr + ks * 32);
            unsigned bfr[16];
            #pragma unroll
            for (int q = 0; q < 4; ++q)
                ldsm4(bfr + 4 * q, b_addr + q * 16 * PSTB + ks * 32);
            #pragma unroll
            for (int nt = 0; nt < 8; ++nt)
                hmma(acc[nt], a, bfr + nt * 2);
        }
    }
    __syncthreads();

    // ---- epilogue: write register partials ----
    {
        float* pa = g_pacc + (size_t)(jq * RT + mt) * BM * FO;
        int row = m0 + (lane >> 2);
        int col = (lane & 3) * 2;
        #pragma unroll
        for (int nt = 0; nt < 8; ++nt) {
            *(float2*)&pa[row * FO + nt * 8 + col] = make_float2(acc[nt][0], acc[nt][1]);
            *(float2*)&pa[(row + 8) * FO + nt * 8 + col] = make_float2(acc[nt][2], acc[nt][3]);
        }
    }
    if (tid < BM) g_pden[(jq * RT + mt) * BM + tid] = sden[tid];
}

// ---------------- Kernel 4: combine partials + ELU ----------------
__global__ __launch_bounds__(256) void combine_kernel(float* __restrict__ out) {
    int idx = blockIdx.x * 256 + threadIdx.x;
    if (idx >= NN * FO) return;
    int i = idx >> 6, c = idx & 63;
    int mt = i >> 7, row = i & 127;
    float a = 0.f, d = 0.f;
    #pragma unroll
    for (int q = 0; q < NSPLIT; ++q) {
        a += g_pacc[(size_t)(q * RT + mt) * BM * FO + row * FO + c];
        d += g_pden[(q * RT + mt) * BM + row];
    }
    float v = a / d;
    out[idx] = v > 0.f ? v : expm1f(v);
}

extern "C" void kernel_launch(void* const* d_in, const int* in_sizes, int n_in,
                              void* d_out, int out_size) {
    const float* h   = (const float*)d_in[0];
    const int*   adj = (const int*)d_in[1];
    const float* W   = (const float*)d_in[2];
    const float* a   = (const float*)d_in[3];
    float* out = (float*)d_out;

    wh_kernel<<<NN / 16, 256>>>(h, W);
    f12_kernel<<<NN / 4, 128>>>(a);

    cudaFuncSetAttribute(gat_mma, cudaFuncAttributeMaxDynamicSharedMemorySize, SM_TOTAL);
    gat_mma<<<dim3(RT, NSPLIT), 256, SM_TOTAL>>>(adj);

    combine_kernel<<<(NN * FO + 255) / 256, 256>>>(out);
}